// round 10
// baseline (speedup 1.0000x reference)
#include <cuda_runtime.h>
#include <cuda_bf16.h>
#include <math.h>

// ChainCRF: B=128, S=256, C=64.
// 64 CTAs x 128 threads; each CTA runs TWO batch chains (A=2c, B=2c+1).
// Thread tau: column j=tau>>1, i-half h=tau&1, for BOTH chains.
// Per pair-step per thread: 2x(4 LDS.128 + 16 fma.rn.f32x2) on a SHARED
// expU register set, 2 shfl.bfly(1), 1 unpredicated STS (h==0 stores A,
// h==1 stores B), one __syncthreads. The two chains' latencies mutually hide.

#define Bc 128
#define Sc 256
#define Cc 64
#define Tc 128
#define Gc (Bc / 2)     // 64 CTAs

__device__ float g_batch_res[Bc];
__device__ unsigned int g_ticket = 0;

#define FMA2(d,a,b,c)  asm("fma.rn.f32x2 %0, %1, %2, %3;" : "=l"(d) : "l"(a), "l"(b), "l"(c))
#define ADD2(d,a,b)    asm("add.rn.f32x2 %0, %1, %2;" : "=l"(d) : "l"(a), "l"(b))
#define PACK2(d,lo,hi) asm("mov.b64 %0, {%1, %2};" : "=l"(d) : "f"(lo), "f"(hi))
#define UNPACK2(lo,hi,s) asm("mov.b64 {%0, %1}, %2;" : "=f"(lo), "=f"(hi) : "l"(s))

// One pair-step: advance chain A and chain B one step each, single barrier.
#define STEP2(QRA, QWA, EXA, QRB, QWB, EXB) do {                               \
    float _q0a = (QRA)[0];                                                     \
    float _q0b = (QRB)[0];                                                     \
    int _ka = (int)((__float_as_uint(_q0a) >> 23) & 0xFF) - 127;               \
    int _kb = (int)((__float_as_uint(_q0b) >> 23) & 0xFF) - 127;               \
    Ka += _ka;  Kb += _kb;                                                     \
    float _emxa = (EXA) * __uint_as_float((unsigned)(127 - _ka) << 23);        \
    float _emxb = (EXB) * __uint_as_float((unsigned)(127 - _kb) << 23);        \
    const ulonglong2* _qva = (const ulonglong2*)((QRA) + hbase);               \
    const ulonglong2* _qvb = (const ulonglong2*)((QRB) + hbase);               \
    unsigned long long _a0 = 0ull, _a1 = 0ull, _b0 = 0ull, _b1 = 0ull;         \
    _Pragma("unroll")                                                          \
    for (int _c = 0; _c < 4; ++_c) {                                           \
        ulonglong2 _va = _qva[_c];                                             \
        ulonglong2 _vb = _qvb[_c];                                             \
        FMA2(_a0, _va.x, rE[4*_c+0], _a0);                                     \
        FMA2(_b0, _vb.x, rE[4*_c+0], _b0);                                     \
        FMA2(_a1, _va.y, rE[4*_c+1], _a1);                                     \
        FMA2(_b1, _vb.y, rE[4*_c+1], _b1);                                     \
        ulonglong2 _wa = _qva[_c + 4];                                         \
        ulonglong2 _wb = _qvb[_c + 4];                                         \
        FMA2(_a0, _wa.x, rE[4*_c+2], _a0);                                     \
        FMA2(_b0, _wb.x, rE[4*_c+2], _b0);                                     \
        FMA2(_a1, _wa.y, rE[4*_c+3], _a1);                                     \
        FMA2(_b1, _wb.y, rE[4*_c+3], _b1);                                     \
    }                                                                          \
    ADD2(_a0, _a0, _a1);                                                       \
    ADD2(_b0, _b0, _b1);                                                       \
    float _alo, _ahi, _blo, _bhi;                                              \
    UNPACK2(_alo, _ahi, _a0);                                                  \
    UNPACK2(_blo, _bhi, _b0);                                                  \
    float _sa = _alo + _ahi;                                                   \
    float _sb = _blo + _bhi;                                                   \
    float _oa = __shfl_xor_sync(0xFFFFFFFFu, _sa, 1);                          \
    float _ob = __shfl_xor_sync(0xFFFFFFFFu, _sb, 1);                          \
    float _ra = (_sa + _oa) * _emxa;                                           \
    float _rb = (_sb + _ob) * _emxb;                                           \
    /* h==0 stores chain A, h==1 stores chain B: one unpredicated STS */       \
    float* _dst = h ? &(QWB)[j] : &(QWA)[j];                                   \
    *_dst = h ? _rb : _ra;                                                     \
    __syncthreads();                                                           \
} while (0)

__global__ __launch_bounds__(Tc, 1)
void crf_kernel(const float* __restrict__ em,
                const int*   __restrict__ tags,
                const float* __restrict__ mask,
                const float* __restrict__ U,
                float* __restrict__ out)
{
    const int c   = blockIdx.x;          // CTA -> batches 2c, 2c+1
    const int tau = threadIdx.x;         // 0..127
    const int j   = tau >> 1;            // column (0..63)
    const int h   = tau & 1;             // i-half
    const int l   = tau & 31;            // lane
    const int w   = tau >> 5;            // warp (0..3)
    const int hbase = 32 * h;

    __shared__ __align__(16) float qa0[Cc], qa1[Cc];
    __shared__ __align__(16) float qb0[Cc], qb1[Cc];
    __shared__ __align__(16) float sU[Cc * Cc];
    __shared__ __align__(16) int   stags[2][Sc];
    __shared__ __align__(16) float smask[2][Sc];
    __shared__ float red[4];

    const int b0 = 2 * c, b1 = 2 * c + 1;

    // ---- stage U, tags, mask into smem (coalesced) ----
    {
        const float4* U4  = (const float4*)U;
        float4*       sU4 = (float4*)sU;
#pragma unroll
        for (int i = 0; i < (Cc * Cc / 4) / Tc; ++i)     // 8 iters
            sU4[tau + Tc * i] = U4[tau + Tc * i];

        int g  = tau >> 6;               // 0 or 1
        int i2 = tau & 63;
        ((int4*)stags[g])[i2]  = ((const int4*)(tags + (size_t)(b0 + g) * Sc))[i2];
        ((float4*)smask[g])[i2] = ((const float4*)(mask + (size_t)(b0 + g) * Sc))[i2];
    }
    __syncthreads();

    // ---- expU half-column (SHARED by both chains): 16 u64 ----
    unsigned long long rE[16];
#pragma unroll
    for (int p = 0; p < 16; ++p) {
        float e0 = __expf(sU[(hbase + 2 * p + 0) * Cc + j]);
        float e1 = __expf(sU[(hbase + 2 * p + 1) * Cc + j]);
        PACK2(rE[p], e0, e1);
    }

    const float* embA = em + (size_t)b0 * Sc * Cc;
    const float* embB = em + (size_t)b1 * Sc * Cc;

    // mask uniformity (both chains)
    int ok = 1;
#pragma unroll
    for (int t = tau; t < Sc; t += Tc)
        ok &= (smask[0][t] == 1.0f) & (smask[1][t] == 1.0f);
    ok = __syncthreads_and(ok);

    // q(0) = exp(em[0]) : h==0 seeds chain A, h==1 seeds chain B
    if (h == 0) qa0[j] = __expf(embA[j]);
    else        qb0[j] = __expf(embB[j]);
    int Ka = 0, Kb = 0;
    __syncthreads();

    if (ok) {
        // ---- fast path: branch-free, deep prefetch per chain ----
        float ra1 = embA[1 * Cc + j], rb1 = embB[1 * Cc + j];
        float a2 = embA[2 * Cc + j], a3 = embA[3 * Cc + j];
        float a4 = embA[4 * Cc + j], a5 = embA[5 * Cc + j];
        float a6 = embA[6 * Cc + j], a7 = embA[7 * Cc + j];
        float b2 = embB[2 * Cc + j], b3 = embB[3 * Cc + j];
        float b4 = embB[4 * Cc + j], b5 = embB[5 * Cc + j];
        float b6 = embB[6 * Cc + j], b7 = embB[7 * Cc + j];

        float exA1 = __expf(ra1), exB1 = __expf(rb1);      // t=1
        float exA0 = __expf(a2),  exB0 = __expf(b2);       // t=2
        float exAo = __expf(a3),  exBo = __expf(b3);       // t=3

        STEP2(qa0, qa1, exA1, qb0, qb1, exB1);             // t = 1

        a2 = a4; a3 = a5; a4 = a6; a5 = a7;
        b2 = b4; b3 = b5; b4 = b6; b5 = b7;

#pragma unroll 1
        for (int t = 2; t < Sc; t += 2) {
            float na6 = (t + 6 < Sc) ? embA[(t + 6) * Cc + j] : 0.0f;
            float na7 = (t + 7 < Sc) ? embA[(t + 7) * Cc + j] : 0.0f;
            float nb6 = (t + 6 < Sc) ? embB[(t + 6) * Cc + j] : 0.0f;
            float nb7 = (t + 7 < Sc) ? embB[(t + 7) * Cc + j] : 0.0f;
            float exAa = __expf(a2), exAb = __expf(a3);    // t+2, t+3
            float exBa = __expf(b2), exBb = __expf(b3);

            STEP2(qa1, qa0, exA0, qb1, qb0, exB0);         // step t   (even)
            STEP2(qa0, qa1, exAo, qb0, qb1, exBo);         // step t+1 (odd)

            exA0 = exAa; exAo = exAb;
            exB0 = exBa; exBo = exBb;
            a2 = a4; a3 = a5; a4 = na6; a5 = na7;
            b2 = b4; b3 = b5; b4 = nb6; b5 = nb7;
        }
        // t=255 (odd) wrote qa1 / qb1
    } else {
        // ---- generic masked fallback (never taken in this dataset) ----
        // h==0 threads advance chain A, h==1 threads advance chain B.
        const float* emg = h ? embB : embA;
        const float* msk = smask[h];
        const float* qr  = h ? qb0 : qa0;
        float*       qw  = h ? qb1 : qa1;
        int Kg = 0;
        for (int t = 1; t < Sc; ++t) {
            float m   = msk[t];
            float emv = emg[t * Cc + j];
            float q0  = qr[0];
            int   k   = (int)((__float_as_uint(q0) >> 23) & 0xFF) - 127;
            float sc  = __uint_as_float((unsigned)(127 - k) << 23);
            Kg += k;

            float s;
            if (m == 1.0f) {
                float a = 0.f;
                for (int i = 0; i < Cc; ++i)
                    a = fmaf(qr[i], __expf(sU[i * Cc + j]), a);
                s = a * __expf(emv);
            } else if (m == 0.0f) {
                float a = 0.f;
                for (int i = 0; i < Cc; ++i) a += qr[i];
                s = a;
            } else {
                float a = 0.f;
                for (int i = 0; i < Cc; ++i)
                    a += qr[i] * __expf((emv + sU[i * Cc + j]) * m);
                s = a;
            }
            qw[j] = s * sc;
            __syncthreads();
            const float* tr = qr; qr = qw; qw = const_cast<float*>(tr);
        }
        if (h == 0) Ka = Kg; else Kb = Kg;
        // propagate K to the partner thread (thread 0 needs Ka, thread 1 Kb)
        int Kother = __shfl_xor_sync(0xFFFFFFFFu, Kg, 1);
        if (h == 0) Kb = Kother; else Ka = Kother;
        // t=255 (odd) wrote qa1/qb1
    }

    // ---- path energy: warps 0-1 -> chain A, warps 2-3 -> chain B ----
    {
        int g   = tau >> 6;              // chain
        int t0  = tau & 63;
        const float* emg = g ? embB : embA;
        const int*   tgg = stags[g];
        const float* msk = smask[g];
        float pe = 0.0f;
#pragma unroll
        for (int t = t0; t < Sc; t += 64) {
            float mt = msk[t];
            int   tg = tgg[t];
            int   tm = (int)((float)tg * mt);
            pe += emg[t * Cc + tm] * mt;
        }
#pragma unroll
        for (int t = 1 + t0; t < Sc; t += 64) {
            pe += sU[tgg[t - 1] * Cc + tgg[t]] * msk[t];
        }
#pragma unroll
        for (int o = 16; o > 0; o >>= 1)
            pe += __shfl_xor_sync(0xFFFFFFFFu, pe, o);
        if (l == 0) red[w] = pe;
    }
    __syncthreads();

    // ---- free energy + per-batch results ----
    if (tau == 0) {
        float qs = 0.0f;
#pragma unroll
        for (int i = 0; i < Cc; ++i) qs += qa1[i];
        float fe = logf(qs) + (float)Ka * 0.6931471805599453f;
        g_batch_res[b0] = fe - (red[0] + red[1]);
        __threadfence();
    }
    if (tau == 1) {
        float qs = 0.0f;
#pragma unroll
        for (int i = 0; i < Cc; ++i) qs += qb1[i];
        float fe = logf(qs) + (float)Kb * 0.6931471805599453f;
        g_batch_res[b1] = fe - (red[2] + red[3]);
        __threadfence();
    }
    __syncthreads();

    // ---- fused finalize: last CTA computes the batch mean ----
    if (w == 0) {
        unsigned int old = 0;
        if (l == 0) old = atomicAdd(&g_ticket, 1u);
        old = __shfl_sync(0xFFFFFFFFu, old, 0);
        if (old == Gc - 1) {
            __threadfence();
            float v = 0.0f;
#pragma unroll
            for (int i = 0; i < Bc / 32; ++i) v += g_batch_res[l + 32 * i];
#pragma unroll
            for (int o = 16; o > 0; o >>= 1)
                v += __shfl_xor_sync(0xFFFFFFFFu, v, o);
            if (l == 0) {
                out[0] = v * (1.0f / (float)Bc);
                g_ticket = 0;              // reset for next graph replay
            }
        }
    }
}

extern "C" void kernel_launch(void* const* d_in, const int* in_sizes, int n_in,
                              void* d_out, int out_size)
{
    const float* emissions = (const float*)d_in[0];
    const int*   true_tags = (const int*)  d_in[1];
    const float* mask      = (const float*)d_in[2];
    const float* U         = (const float*)d_in[3];
    float* out = (float*)d_out;

    crf_kernel<<<Gc, Tc>>>(emissions, true_tags, mask, U, out);
}

// round 12
// speedup vs baseline: 1.6532x; 1.6532x over previous
#include <cuda_runtime.h>
#include <cuda_bf16.h>
#include <math.h>

// ChainCRF: B=128, S=256, C=64.
// TWO WARPS per batch row (128 CTAs x 64 threads). Thread j owns column j.
// Linear-domain forward recursion; log taken once at the end.
// Power-of-two renorm every 4 steps (exact scaling, fp32 range analysis:
// <=~2^15 growth/step -> 4 steps safe), folded into that step's emission
// multiplier. Per step: 16 broadcast LDS.128, 32 fma.rn.f32x2 in FOUR
// dependency chains, STS.32, one __syncthreads.

#define Bc 128
#define Sc 256
#define Cc 64
#define Tc 64

__device__ float g_batch_res[Bc];
__device__ unsigned int g_ticket = 0;

#define FMA2(d,a,b,c)  asm("fma.rn.f32x2 %0, %1, %2, %3;" : "=l"(d) : "l"(a), "l"(b), "l"(c))
#define ADD2(d,a,b)    asm("add.rn.f32x2 %0, %1, %2;" : "=l"(d) : "l"(a), "l"(b))
#define PACK2(d,lo,hi) asm("mov.b64 %0, {%1, %2};" : "=l"(d) : "f"(lo), "f"(hi))
#define UNPACK2(lo,hi,s) asm("mov.b64 {%0, %1}, %2;" : "=f"(lo), "=f"(hi) : "l"(s))

// Core step: q_new[j] = (sum_i q_i * expU[i][j]) * EMXV.  4 accumulator chains.
#define STEP_CORE(QR, QW, EMXV) do {                                           \
    unsigned long long _a0 = 0ull, _a1 = 0ull, _a2 = 0ull, _a3 = 0ull;         \
    const ulonglong2* _qv = (const ulonglong2*)(QR);                           \
    _Pragma("unroll")                                                          \
    for (int _c = 0; _c < 8; ++_c) {                                           \
        ulonglong2 _v = _qv[2 * _c];                                           \
        ulonglong2 _w = _qv[2 * _c + 1];                                       \
        FMA2(_a0, _v.x, rE[4*_c+0], _a0);                                      \
        FMA2(_a1, _v.y, rE[4*_c+1], _a1);                                      \
        FMA2(_a2, _w.x, rE[4*_c+2], _a2);                                      \
        FMA2(_a3, _w.y, rE[4*_c+3], _a3);                                      \
    }                                                                          \
    ADD2(_a0, _a0, _a1);                                                       \
    ADD2(_a2, _a2, _a3);                                                       \
    ADD2(_a0, _a0, _a2);                                                       \
    float _lo, _hi;                                                            \
    UNPACK2(_lo, _hi, _a0);                                                    \
    (QW)[j] = (_lo + _hi) * (EMXV);                                            \
    __syncthreads();                                                           \
} while (0)

// Renormalizing step: extract q[0]'s exponent, fold exact 2^-k into EMX.
#define STEP_R(QR, QW, EX) do {                                                \
    float _q0 = (QR)[0];                                                       \
    int   _k  = (int)((__float_as_uint(_q0) >> 23) & 0xFF) - 127;              \
    K += _k;                                                                   \
    float _emx = (EX) * __uint_as_float((unsigned)(127 - _k) << 23);           \
    STEP_CORE(QR, QW, _emx);                                                   \
} while (0)

#define STEP_N(QR, QW, EX) STEP_CORE(QR, QW, (EX))

__global__ __launch_bounds__(Tc, 1)
void crf_kernel(const float* __restrict__ em,
                const int*   __restrict__ tags,
                const float* __restrict__ mask,
                const float* __restrict__ U,
                float* __restrict__ out)
{
    const int b = blockIdx.x;
    const int j = threadIdx.x;           // column owned by this thread (0..63)
    const int l = j & 31;                // lane
    const int w = j >> 5;                // warp (0,1)

    __shared__ __align__(16) float qA[Cc];
    __shared__ __align__(16) float qB[Cc];
    __shared__ __align__(16) float sU[Cc * Cc];
    __shared__ __align__(16) int   stags[Sc];
    __shared__ __align__(16) float smask[Sc];
    __shared__ float red[2];

    // ---- stage U, tags, mask into smem (coalesced) ----
    {
        const float4* U4  = (const float4*)U;
        float4*       sU4 = (float4*)sU;
#pragma unroll
        for (int i = 0; i < (Cc * Cc / 4) / Tc; ++i)     // 16 iters
            sU4[j + Tc * i] = U4[j + Tc * i];

        ((int4*)stags)[j]  = ((const int4*)(tags + (size_t)b * Sc))[j];
        ((float4*)smask)[j] = ((const float4*)(mask + (size_t)b * Sc))[j];
    }
    __syncthreads();

    // ---- expU column j packed over i-pairs: 32 u64 registers ----
    unsigned long long rE[32];
#pragma unroll
    for (int p = 0; p < 32; ++p) {
        float e0 = __expf(sU[(2 * p + 0) * Cc + j]);
        float e1 = __expf(sU[(2 * p + 1) * Cc + j]);
        PACK2(rE[p], e0, e1);            // {E[2p][j], E[2p+1][j]}
    }

    const float* emb = em + (size_t)b * Sc * Cc;   // em[t][j] = emb[t*64 + j]

    // mask uniformity check (hoists the branch out of the hot loop)
    int ok = 1;
#pragma unroll
    for (int t = j; t < Sc; t += Tc) ok &= (smask[t] == 1.0f);
    ok = __syncthreads_and(ok);

    // q(0) = exp(em[0])
    qA[j] = __expf(emb[j]);
    int K = 0;
    __syncthreads();

    if (ok) {
        // ---- fast path: 4-step chunks, renorm once per chunk ----
        float c0 = emb[1 * Cc + j], c1 = emb[2 * Cc + j], c2 = emb[3 * Cc + j];
        float ex0 = __expf(c0), ex1 = __expf(c1), ex2 = __expf(c2);
        float d0 = emb[4 * Cc + j], d1 = emb[5 * Cc + j];
        float d2 = emb[6 * Cc + j], d3 = emb[7 * Cc + j];

        STEP_R(qA, qB, ex0);             // t = 1  (renorm)
        STEP_N(qB, qA, ex1);             // t = 2
        STEP_N(qA, qB, ex2);             // t = 3

#pragma unroll 1
        for (int t = 4; t < Sc; t += 4) {
            float e0 = __expf(d0), e1 = __expf(d1);
            float e2 = __expf(d2), e3 = __expf(d3);
            float n0 = (t + 4 < Sc) ? emb[(t + 4) * Cc + j] : 0.0f;
            float n1 = (t + 5 < Sc) ? emb[(t + 5) * Cc + j] : 0.0f;
            float n2 = (t + 6 < Sc) ? emb[(t + 6) * Cc + j] : 0.0f;
            float n3 = (t + 7 < Sc) ? emb[(t + 7) * Cc + j] : 0.0f;

            STEP_R(qB, qA, e0);          // t     (renorm)
            STEP_N(qA, qB, e1);          // t + 1
            STEP_N(qB, qA, e2);          // t + 2
            STEP_N(qA, qB, e3);          // t + 3

            d0 = n0; d1 = n1; d2 = n2; d3 = n3;
        }
        // t=255 wrote qB
    } else {
        // ---- generic masked fallback (never taken in this dataset) ----
        const float* qr = qA; float* qw = qB;
        for (int t = 1; t < Sc; ++t) {
            float m   = smask[t];
            float emv = emb[t * Cc + j];
            float q0  = qr[0];
            int   k   = (int)((__float_as_uint(q0) >> 23) & 0xFF) - 127;
            float sc  = __uint_as_float((unsigned)(127 - k) << 23);
            K += k;

            float s;
            if (m == 1.0f) {
                float a = 0.f;
                for (int i = 0; i < Cc; ++i)
                    a = fmaf(qr[i], __expf(sU[i * Cc + j]), a);
                s = a * __expf(emv);
            } else if (m == 0.0f) {
                float a = 0.f;
                for (int i = 0; i < Cc; ++i) a += qr[i];
                s = a;
            } else {
                float a = 0.f;
                for (int i = 0; i < Cc; ++i)
                    a += qr[i] * __expf((emv + sU[i * Cc + j]) * m);
                s = a;
            }
            qw[j] = s * sc;
            __syncthreads();
            const float* tr = qr; qr = qw; qw = const_cast<float*>(tr);
        }
        // t=255 (odd) wrote qB
    }

    // ---- path energy ----
    float pe = 0.0f;
#pragma unroll
    for (int t = j; t < Sc; t += Tc) {
        float mt = smask[t];
        int   tg = stags[t];
        int   tm = (int)((float)tg * mt);
        pe += emb[t * Cc + tm] * mt;
    }
#pragma unroll
    for (int t = 1 + j; t < Sc; t += Tc) {
        pe += sU[stags[t - 1] * Cc + stags[t]] * smask[t];
    }
#pragma unroll
    for (int o = 16; o > 0; o >>= 1)
        pe += __shfl_xor_sync(0xFFFFFFFFu, pe, o);
    if (l == 0) red[w] = pe;
    __syncthreads();

    // ---- free energy + per-batch result + fused finalize ----
    if (j == 0) {
        float qs = 0.0f;
#pragma unroll
        for (int i = 0; i < Cc; ++i) qs += qB[i];
        float fe = logf(qs) + (float)K * 0.6931471805599453f;
        g_batch_res[b] = fe - (red[0] + red[1]);
        __threadfence();
    }
    __syncthreads();

    if (w == 0) {
        unsigned int old = 0;
        if (l == 0) old = atomicAdd(&g_ticket, 1u);
        old = __shfl_sync(0xFFFFFFFFu, old, 0);
        if (old == Bc - 1) {
            __threadfence();
            float v = 0.0f;
#pragma unroll
            for (int i = 0; i < Bc / 32; ++i) v += g_batch_res[l + 32 * i];
#pragma unroll
            for (int o = 16; o > 0; o >>= 1)
                v += __shfl_xor_sync(0xFFFFFFFFu, v, o);
            if (l == 0) {
                out[0] = v * (1.0f / (float)Bc);
                g_ticket = 0;              // reset for next graph replay
            }
        }
    }
}

extern "C" void kernel_launch(void* const* d_in, const int* in_sizes, int n_in,
                              void* d_out, int out_size)
{
    const float* emissions = (const float*)d_in[0];
    const int*   true_tags = (const int*)  d_in[1];
    const float* mask      = (const float*)d_in[2];
    const float* U         = (const float*)d_in[3];
    float* out = (float*)d_out;

    crf_kernel<<<Bc, Tc>>>(emissions, true_tags, mask, U, out);
}